// round 11
// baseline (speedup 1.0000x reference)
#include <cuda_runtime.h>
#include <cuda_bf16.h>
#include <math.h>
#include <stdint.h>

#define Bn 32
#define Ln 32
#define NCc 528
#define Dd 384
#define MAXP 32768
#define WELEM (384*384)

// ---------------- device scratch (static, allocation-rule-safe) ----------------
__device__ float g_A [(size_t)Bn*NCc*Dd];   // cell @ W0   (inside) / parent @ out_W0 (outside)
__device__ float g_Bb[(size_t)Bn*NCc*Dd];   // cell @ W1   (inside) / sib @ out_W1   (outside)
__device__ float g_Cm[(size_t)Bn*NCc*Dd];   // cell @ bi   (inside) / sib @ out_bi   (outside)
__device__ float g_H [(size_t)MAXP*Dd];     // per-pair h
__device__ float g_X [(size_t)MAXP*Dd];     // per-pair xc
__device__ float g_P [MAXP];                // per-pair softmax weight
// 9 weight matrices, each as EXACT 3-way bf16 split (h,m,l) in [n][k] layout
__device__ __nv_bfloat16 g_Wb[(size_t)9*3*WELEM];

__host__ __device__ __forceinline__ int offi(int l){ return l*Ln - (l*(l-1))/2; }

__device__ __forceinline__ float sigma_h_f(float x){
    float s = 1.f/(1.f+expf(-x));
    return x * tanhf(sqrtf(s));
}

__device__ __forceinline__ void in_idx(int level,int pos,int n,int&li,int&ri){
    li = offi(n) + pos;
    ri = offi(level-n-1) + pos + n + 1;
}
__device__ __forceinline__ void out_idx(int level,int pos,int n,int&par,int&sib){
    int T1 = Ln - pos - level - 1;
    if (n < T1){ par = offi(level+n+1)+pos;     sib = offi(n)+pos+level+1; }
    else { int s = n - T1; par = offi(level+s+1)+pos-s-1; sib = offi(s)+pos-s-1; }
}

// EXACT 3-way bf16 split of two fp32 values (packed bf16x2 each):
// x = h + m + l exactly (8+8+8 mantissa bits >= 24; each residual subtraction exact)
__device__ __forceinline__ void cvt3(float x0, float x1, uint32_t& h, uint32_t& m, uint32_t& l){
    asm("cvt.rn.bf16x2.f32 %0, %1, %2;" : "=r"(h) : "f"(x1), "f"(x0));
    float h0 = __uint_as_float(h << 16);
    float h1 = __uint_as_float(h & 0xffff0000u);
    float r0 = x0 - h0, r1 = x1 - h1;
    asm("cvt.rn.bf16x2.f32 %0, %1, %2;" : "=r"(m) : "f"(r1), "f"(r0));
    float m0 = __uint_as_float(m << 16);
    float m1 = __uint_as_float(m & 0xffff0000u);
    float s0 = r0 - m0, s1 = r1 - m1;
    asm("cvt.rn.bf16x2.f32 %0, %1, %2;" : "=r"(l) : "f"(s1), "f"(s0));
}

__device__ __forceinline__ void mma_bf16(float* c, const uint32_t* a, const uint32_t* b){
    asm("mma.sync.aligned.m16n8k16.row.col.f32.bf16.bf16.f32 "
        "{%0,%1,%2,%3}, {%4,%5,%6,%7}, {%8,%9}, {%0,%1,%2,%3};"
        : "+f"(c[0]), "+f"(c[1]), "+f"(c[2]), "+f"(c[3])
        : "r"(a[0]), "r"(a[1]), "r"(a[2]), "r"(a[3]), "r"(b[0]), "r"(b[1]));
}

// 128-thread block reduce of (sum, sumsq)
__device__ __forceinline__ void blockReduce2_128(float& s, float& q){
    __shared__ float shm[8];
    #pragma unroll
    for (int o=16;o>0;o>>=1){
        s += __shfl_xor_sync(0xffffffffu, s, o);
        q += __shfl_xor_sync(0xffffffffu, q, o);
    }
    int w = threadIdx.x>>5;
    if ((threadIdx.x&31)==0){ shm[w]=s; shm[4+w]=q; }
    __syncthreads();
    s = shm[0]+shm[1]+shm[2]+shm[3];
    q = shm[4]+shm[5]+shm[6]+shm[7];
    __syncthreads();
}

// ---------------- weight split: W[k][n] fp32 -> [n][k] bf16 h/m/l (exact) ----------------
struct WP { const float* W[9]; };

__global__ void __launch_bounds__(256) convw_k(WP wp, __nv_bfloat16* out){
    int mtx = blockIdx.y;
    int idx = blockIdx.x*256 + threadIdx.x;   // idx = n*384 + k
    int n = idx / Dd, k = idx - n*Dd;
    float x = wp.W[mtx][(size_t)k*Dd + n];
    __nv_bfloat16 h = __float2bfloat16(x);
    float r = x - __bfloat162float(h);
    __nv_bfloat16 m = __float2bfloat16(r);
    float s = r - __bfloat162float(m);
    __nv_bfloat16 l = __float2bfloat16(s);
    size_t base = (size_t)mtx*3*WELEM;
    out[base + idx]           = h;
    out[base + WELEM + idx]   = m;
    out[base + 2*WELEM + idx] = l;
}

// ---------------- bf16x8 (exact-split, split accumulators) TC GEMM (K=N=384) ----------
// row r -> global row g = (r/Ls)*bstride + cellOff + (r%Ls); dense: Ls=rows,bstride=0,cellOff=0
struct GM { const __nv_bfloat16* Wh[3]; const __nv_bfloat16* Wm[3]; const __nv_bfloat16* Wl[3]; float* C[3]; };

__global__ void __launch_bounds__(256) gemm_k(
    const float* __restrict__ Abase, GM gm, const float* __restrict__ bias,
    int rows, int Ls, int bstride, int cellOff, int epi)
{
    const __nv_bfloat16* __restrict__ Wh = gm.Wh[blockIdx.z];
    const __nv_bfloat16* __restrict__ Wm = gm.Wm[blockIdx.z];
    const __nv_bfloat16* __restrict__ Wl = gm.Wl[blockIdx.z];
    float* __restrict__ Cb = gm.C[blockIdx.z];

    // k-stride padded to 24 bf16 (48B)
    __shared__ __align__(16) __nv_bfloat16 Ash[128*24];
    __shared__ __align__(16) __nv_bfloat16 Asm[128*24];
    __shared__ __align__(16) __nv_bfloat16 Asl[128*24];
    __shared__ __align__(16) __nv_bfloat16 Bsh[128*24];
    __shared__ __align__(16) __nv_bfloat16 Bsm[128*24];
    __shared__ __align__(16) __nv_bfloat16 Bsl[128*24];

    const int tid = threadIdx.x;
    const int bm = blockIdx.x<<7, bn = blockIdx.y<<7;
    const int ar = tid & 127;            // row (A) / n (B) within tile
    const int ak = (tid >> 7) << 3;      // k-half: 0 or 8

    const float* Ap = nullptr;
    { int r = bm + ar;
      if (r < rows){ int b = r / Ls; int p = r - b*Ls;
        Ap = Abase + (size_t)(b*bstride + cellOff + p)*Dd + ak; } }
    const __nv_bfloat16* Bph = Wh + (size_t)(bn + ar)*Dd + ak;
    const __nv_bfloat16* Bpm = Wm + (size_t)(bn + ar)*Dd + ak;
    const __nv_bfloat16* Bpl = Wl + (size_t)(bn + ar)*Dd + ak;

    // Cr: hh only (fp32-equivalent rounding count). Cd: all corrections (small magnitude).
    float Cr[4][4][4], Cd[4][4][4];
    #pragma unroll
    for (int i=0;i<4;i++)
        #pragma unroll
        for (int j=0;j<4;j++)
            #pragma unroll
            for (int q=0;q<4;q++){ Cr[i][j][q]=0.f; Cd[i][j][q]=0.f; }

    const int wid = tid>>5, lane = tid&31;
    const int wm = (wid>>2)<<6;          // 0 or 64
    const int wn = (wid&3)<<5;           // 0,32,64,96
    const int g = lane>>2, tg = lane&3;

    uint32_t ha[4], ma[4], la[4]; uint4 bhv, bmv, blv;
    // prologue: stage chunk 0
    {
        float4 a0v = make_float4(0.f,0.f,0.f,0.f), a1v = a0v;
        if (Ap){ a0v = *(const float4*)(Ap); a1v = *(const float4*)(Ap + 4); }
        cvt3(a0v.x, a0v.y, ha[0], ma[0], la[0]);
        cvt3(a0v.z, a0v.w, ha[1], ma[1], la[1]);
        cvt3(a1v.x, a1v.y, ha[2], ma[2], la[2]);
        cvt3(a1v.z, a1v.w, ha[3], ma[3], la[3]);
        bhv = *(const uint4*)(Bph);
        bmv = *(const uint4*)(Bpm);
        blv = *(const uint4*)(Bpl);
    }

    for (int k0=0; k0<Dd; k0+=16){
        *(uint4*)&Ash[ar*24+ak] = make_uint4(ha[0],ha[1],ha[2],ha[3]);
        *(uint4*)&Asm[ar*24+ak] = make_uint4(ma[0],ma[1],ma[2],ma[3]);
        *(uint4*)&Asl[ar*24+ak] = make_uint4(la[0],la[1],la[2],la[3]);
        *(uint4*)&Bsh[ar*24+ak] = bhv;
        *(uint4*)&Bsm[ar*24+ak] = bmv;
        *(uint4*)&Bsl[ar*24+ak] = blv;
        __syncthreads();

        if (k0 + 16 < Dd){
            float4 a0v = make_float4(0.f,0.f,0.f,0.f), a1v = a0v;
            if (Ap){ a0v = *(const float4*)(Ap + k0 + 16); a1v = *(const float4*)(Ap + k0 + 20); }
            cvt3(a0v.x, a0v.y, ha[0], ma[0], la[0]);
            cvt3(a0v.z, a0v.w, ha[1], ma[1], la[1]);
            cvt3(a1v.x, a1v.y, ha[2], ma[2], la[2]);
            cvt3(a1v.z, a1v.w, ha[3], ma[3], la[3]);
            bhv = *(const uint4*)(Bph + k0 + 16);
            bmv = *(const uint4*)(Bpm + k0 + 16);
            blv = *(const uint4*)(Bpl + k0 + 16);
        }

        // B fragments resident (24 regs)
        uint32_t Bh[4][2], Bm2[4][2], Bl[4][2];
        #pragma unroll
        for (int ni=0;ni<4;ni++){
            int c0 = (wn + ni*8 + g)*24 + tg*2;
            Bh[ni][0]  = *(const uint32_t*)&Bsh[c0];
            Bh[ni][1]  = *(const uint32_t*)&Bsh[c0 + 8];
            Bm2[ni][0] = *(const uint32_t*)&Bsm[c0];
            Bm2[ni][1] = *(const uint32_t*)&Bsm[c0 + 8];
            Bl[ni][0]  = *(const uint32_t*)&Bsl[c0];
            Bl[ni][1]  = *(const uint32_t*)&Bsl[c0 + 8];
        }

        // A fragments loaded per-mi (12 regs live) to cap register pressure
        #pragma unroll
        for (int mi=0;mi<4;mi++){
            int r0 = (wm + mi*16 + g)*24 + tg*2;
            uint32_t Ah[4], Am[4], Al[4];
            Ah[0] = *(const uint32_t*)&Ash[r0];
            Ah[1] = *(const uint32_t*)&Ash[r0 + 8*24];
            Ah[2] = *(const uint32_t*)&Ash[r0 + 8];
            Ah[3] = *(const uint32_t*)&Ash[r0 + 8*24 + 8];
            Am[0] = *(const uint32_t*)&Asm[r0];
            Am[1] = *(const uint32_t*)&Asm[r0 + 8*24];
            Am[2] = *(const uint32_t*)&Asm[r0 + 8];
            Am[3] = *(const uint32_t*)&Asm[r0 + 8*24 + 8];
            Al[0] = *(const uint32_t*)&Asl[r0];
            Al[1] = *(const uint32_t*)&Asl[r0 + 8*24];
            Al[2] = *(const uint32_t*)&Asl[r0 + 8];
            Al[3] = *(const uint32_t*)&Asl[r0 + 8*24 + 8];

            // 8 products; only ll (~2^-36) dropped.
            // hh -> Cr (isolated, fp32-equivalent accumulation); rest -> Cd.
            #pragma unroll
            for (int ni=0;ni<4;ni++){
                mma_bf16(Cr[mi][ni], Ah, Bh[ni]);
                mma_bf16(Cd[mi][ni], Ah, Bm2[ni]);
                mma_bf16(Cd[mi][ni], Am, Bh[ni]);
                mma_bf16(Cd[mi][ni], Am, Bm2[ni]);
                mma_bf16(Cd[mi][ni], Ah, Bl[ni]);
                mma_bf16(Cd[mi][ni], Al, Bh[ni]);
                mma_bf16(Cd[mi][ni], Am, Bl[ni]);
                mma_bf16(Cd[mi][ni], Al, Bm2[ni]);
            }
        }
        __syncthreads();
    }

    // ---- epilogue: single merge add per element ----
    #pragma unroll
    for (int mi=0;mi<4;mi++){
        #pragma unroll
        for (int half=0; half<2; half++){
            int r = bm + wm + mi*16 + g + half*8;
            if (r < rows){
                int b = r / Ls; int p = r - b*Ls;
                float* Crow = Cb + (size_t)(b*bstride + cellOff + p)*Dd + bn + wn;
                #pragma unroll
                for (int ni=0;ni<4;ni++){
                    int c0 = ni*8 + tg*2;
                    float v0 = Cr[mi][ni][half*2+0] + Cd[mi][ni][half*2+0];
                    float v1 = Cr[mi][ni][half*2+1] + Cd[mi][ni][half*2+1];
                    if (epi){
                        v0 = sigma_h_f(v0 + bias[bn+wn+c0]);
                        v1 = sigma_h_f(v1 + bias[bn+wn+c0+1]);
                    }
                    *(float2*)(Crow + c0) = make_float2(v0, v1);
                }
            }
        }
    }
}

// ---------------- score + softmax kernels ----------------
__global__ void __launch_bounds__(256) score_in_k(
    const float* __restrict__ ih, float* __restrict__ isb,
    const float* __restrict__ cM, float* __restrict__ P, int level)
{
    int Ls = Ln - level;
    int bp = blockIdx.x;
    int b = bp / Ls, pos = bp - b*Ls;
    int warp = threadIdx.x >> 5, lane = threadIdx.x & 31;
    __shared__ float sc[32];
    for (int n = warp; n < level; n += 8){
        int li, ri; in_idx(level, pos, n, li, ri);
        const float* u = cM + (size_t)(b*NCc + li)*Dd;
        const float* v = ih + (size_t)(b*NCc + ri)*Dd;
        float s = 0.f;
        #pragma unroll 4
        for (int d = lane; d < Dd; d += 32) s += u[d]*v[d];
        #pragma unroll
        for (int o=16;o>0;o>>=1) s += __shfl_xor_sync(0xffffffffu, s, o);
        if (lane==0) sc[n] = s + isb[b*NCc+li] + isb[b*NCc+ri];
    }
    __syncthreads();
    if (warp==0){
        float v = (lane < level) ? sc[lane] : -1e30f;
        float m = v;
        #pragma unroll
        for (int o=16;o>0;o>>=1) m = fmaxf(m, __shfl_xor_sync(0xffffffffu, m, o));
        float e = (lane < level) ? expf(v - m) : 0.f;
        float se = e;
        #pragma unroll
        for (int o=16;o>0;o>>=1) se += __shfl_xor_sync(0xffffffffu, se, o);
        float p = e / se;
        float pb = (lane < level) ? p * v : 0.f;
        #pragma unroll
        for (int o=16;o>0;o>>=1) pb += __shfl_xor_sync(0xffffffffu, pb, o);
        if (lane < level) P[(size_t)bp*level + lane] = p;
        if (lane==0) isb[b*NCc + offi(level) + pos] = pb;
    }
}

__global__ void __launch_bounds__(256) score_out_k(
    const float* __restrict__ oh, float* __restrict__ osb,
    const float* __restrict__ isb, const float* __restrict__ cM,
    float* __restrict__ P, int level)
{
    int Ls = Ln - level, N = Ln - level - 1;
    int bp = blockIdx.x;
    int b = bp / Ls, pos = bp - b*Ls;
    int warp = threadIdx.x >> 5, lane = threadIdx.x & 31;
    __shared__ float sc[32];
    for (int n = warp; n < N; n += 8){
        int par, sib; out_idx(level, pos, n, par, sib);
        const float* u = cM + (size_t)(b*NCc + sib)*Dd;
        const float* v = oh + (size_t)(b*NCc + par)*Dd;
        float s = 0.f;
        #pragma unroll 4
        for (int d = lane; d < Dd; d += 32) s += u[d]*v[d];
        #pragma unroll
        for (int o=16;o>0;o>>=1) s += __shfl_xor_sync(0xffffffffu, s, o);
        if (lane==0) sc[n] = s + isb[b*NCc+sib] + osb[b*NCc+par];
    }
    __syncthreads();
    if (warp==0){
        float v = (lane < N) ? sc[lane] : -1e30f;
        float m = v;
        #pragma unroll
        for (int o=16;o>0;o>>=1) m = fmaxf(m, __shfl_xor_sync(0xffffffffu, m, o));
        float e = (lane < N) ? expf(v - m) : 0.f;
        float se = e;
        #pragma unroll
        for (int o=16;o>0;o>>=1) se += __shfl_xor_sync(0xffffffffu, se, o);
        float p = e / se;
        float pb = (lane < N) ? p * v : 0.f;
        #pragma unroll
        for (int o=16;o>0;o>>=1) pb += __shfl_xor_sync(0xffffffffu, pb, o);
        if (lane < N) P[(size_t)bp*N + lane] = p;
        if (lane==0) osb[b*NCc + offi(level) + pos] = pb;
    }
}

// ---------------- per-pair h = sigma_h(A[a] + B[b] + b0) ----------------
__global__ void __launch_bounds__(384) h_k(
    const float* __restrict__ Abuf, const float* __restrict__ Bbuf,
    const float* __restrict__ b0, float* __restrict__ H,
    int level, int nC, int Ls, int outside, int Pn)
{
    int pl = threadIdx.x / 96;
    int d  = threadIdx.x - pl*96;
    int pair = blockIdx.x*4 + pl;
    if (pair >= Pn) return;
    int bp = pair / nC, n = pair - bp*nC;
    int b = bp / Ls, pos = bp - b*Ls;
    int ia, ib;
    if (!outside) in_idx(level, pos, n, ia, ib);
    else          out_idx(level, pos, n, ia, ib);
    const float4* a  = (const float4*)(Abuf + (size_t)(b*NCc+ia)*Dd);
    const float4* bb = (const float4*)(Bbuf + (size_t)(b*NCc+ib)*Dd);
    const float4* bi = (const float4*)b0;
    float4 av = a[d], bv = bb[d], cv = bi[d];
    float4 h;
    h.x = sigma_h_f(av.x+bv.x+cv.x);
    h.y = sigma_h_f(av.y+bv.y+cv.y);
    h.z = sigma_h_f(av.z+bv.z+cv.z);
    h.w = sigma_h_f(av.w+bv.w+cv.w);
    ((float4*)(H + (size_t)pair*Dd))[d] = h;
}

// ---------------- p-weighted sum over candidates + layer_norm ----------------
__global__ void __launch_bounds__(128) reduceln_k(
    const float* __restrict__ XC, const float* __restrict__ P,
    const float* __restrict__ gamma, const float* __restrict__ beta,
    float* __restrict__ out, int nC, int Ls, int cellOff)
{
    int bp = blockIdx.x;
    int b = bp / Ls, pos = bp - b*Ls;
    int t = threadIdx.x;
    float a0=0.f, a1=0.f, a2=0.f;
    const float* xrow = XC + (size_t)bp*nC*Dd;
    for (int n=0;n<nC;n++){
        float p = P[(size_t)bp*nC + n];
        const float* x = xrow + (size_t)n*Dd;
        a0 += p*x[t]; a1 += p*x[t+128]; a2 += p*x[t+256];
    }
    float s = a0+a1+a2;
    float q = a0*a0+a1*a1+a2*a2;
    blockReduce2_128(s, q);
    float mu = s * (1.f/384.f);
    float var = q * (1.f/384.f) - mu*mu;
    float r = rsqrtf(var + 1e-5f);
    float* o = out + (size_t)(b*NCc + cellOff + pos)*Dd;
    o[t]     = (a0-mu)*r*gamma[t]     + beta[t];
    o[t+128] = (a1-mu)*r*gamma[t+128] + beta[t+128];
    o[t+256] = (a2-mu)*r*gamma[t+256] + beta[t+256];
}

// ---------------- leaf: sigma_h(pre + leaf_b) -> layer_norm -> ih; zero is_ ----------------
__global__ void __launch_bounds__(128) leaf_k(
    const float* __restrict__ pre, const float* __restrict__ lb,
    const float* __restrict__ gamma, const float* __restrict__ beta,
    float* __restrict__ ih, float* __restrict__ isb)
{
    int row = blockIdx.x;         // B*32
    int b = row >> 5, pos = row & 31;
    int t = threadIdx.x;
    const float* pr = pre + (size_t)row*Dd;
    float a0 = sigma_h_f(pr[t]     + lb[t]);
    float a1 = sigma_h_f(pr[t+128] + lb[t+128]);
    float a2 = sigma_h_f(pr[t+256] + lb[t+256]);
    float s = a0+a1+a2, q = a0*a0+a1*a1+a2*a2;
    blockReduce2_128(s, q);
    float mu = s * (1.f/384.f);
    float var = q * (1.f/384.f) - mu*mu;
    float r = rsqrtf(var + 1e-5f);
    float* o = ih + (size_t)(b*NCc + pos)*Dd;
    o[t]     = (a0-mu)*r*gamma[t]     + beta[t];
    o[t+128] = (a1-mu)*r*gamma[t+128] + beta[t+128];
    o[t+256] = (a2-mu)*r*gamma[t+256] + beta[t+256];
    if (t==0) isb[b*NCc + pos] = 0.f;
}

// ---------------- root: oh[:, -1] = layer_norm(root_h); os[:, -1] = 0 ----------------
__global__ void __launch_bounds__(128) root_k(
    const float* __restrict__ rh,
    const float* __restrict__ gamma, const float* __restrict__ beta,
    float* __restrict__ oh, float* __restrict__ osb)
{
    int b = blockIdx.x;
    int t = threadIdx.x;
    float a0 = rh[t], a1 = rh[t+128], a2 = rh[t+256];
    float s = a0+a1+a2, q = a0*a0+a1*a1+a2*a2;
    blockReduce2_128(s, q);
    float mu = s * (1.f/384.f);
    float var = q * (1.f/384.f) - mu*mu;
    float r = rsqrtf(var + 1e-5f);
    float* o = oh + (size_t)(b*NCc + NCc-1)*Dd;
    o[t]     = (a0-mu)*r*gamma[t]     + beta[t];
    o[t+128] = (a1-mu)*r*gamma[t+128] + beta[t+128];
    o[t+256] = (a2-mu)*r*gamma[t+256] + beta[t+256];
    if (t==0) osb[b*NCc + NCc-1] = 0.f;
}

// ---------------- orchestration ----------------
extern "C" void kernel_launch(void* const* d_in, const int* in_sizes, int n_in,
                              void* d_out, int out_size)
{
    (void)in_sizes; (void)n_in; (void)out_size;
    const float* x        = (const float*)d_in[0];
    const float* leaf_W   = (const float*)d_in[1];
    const float* leaf_b   = (const float*)d_in[2];
    const float* in_ln_g  = (const float*)d_in[3];
    const float* in_ln_b  = (const float*)d_in[4];
    const float* out_ln_g = (const float*)d_in[5];
    const float* out_ln_b = (const float*)d_in[6];
    const float* root_h   = (const float*)d_in[7];
    const float* in_bi    = (const float*)d_in[8];
    const float* out_bi   = (const float*)d_in[9];
    const float* in_W0    = (const float*)d_in[10];
    const float* in_W1    = (const float*)d_in[11];
    const float* in_B0    = (const float*)d_in[12];
    const float* in_W2    = (const float*)d_in[13];
    const float* in_B1    = (const float*)d_in[14];
    const float* out_W0   = (const float*)d_in[15];
    const float* out_W1   = (const float*)d_in[16];
    const float* out_B0   = (const float*)d_in[17];
    const float* out_W2   = (const float*)d_in[18];
    const float* out_B1   = (const float*)d_in[19];

    float* ih  = (float*)d_out;
    float* isb = ih  + (size_t)Bn*NCc*Dd;
    float* oh  = isb + (size_t)Bn*NCc;
    float* osb = oh  + (size_t)Bn*NCc*Dd;

    float *A,*Bb,*Cm,*H,*X,*P; __nv_bfloat16* Wb;
    cudaGetSymbolAddress((void**)&A,  g_A);
    cudaGetSymbolAddress((void**)&Bb, g_Bb);
    cudaGetSymbolAddress((void**)&Cm, g_Cm);
    cudaGetSymbolAddress((void**)&H,  g_H);
    cudaGetSymbolAddress((void**)&X,  g_X);
    cudaGetSymbolAddress((void**)&P,  g_P);
    cudaGetSymbolAddress((void**)&Wb, g_Wb);

    // matrix order: 0 leaf_W, 1 in_W0, 2 in_W1, 3 in_bi, 4 in_W2,
    //               5 out_W0, 6 out_W1, 7 out_bi, 8 out_W2
    auto WH = [&](int m){ return (const __nv_bfloat16*)(Wb + (size_t)m*3*WELEM); };
    auto WM = [&](int m){ return (const __nv_bfloat16*)(Wb + (size_t)m*3*WELEM + WELEM); };
    auto WL = [&](int m){ return (const __nv_bfloat16*)(Wb + (size_t)m*3*WELEM + 2*WELEM); };

    {
        WP wp;
        wp.W[0]=leaf_W; wp.W[1]=in_W0; wp.W[2]=in_W1; wp.W[3]=in_bi; wp.W[4]=in_W2;
        wp.W[5]=out_W0; wp.W[6]=out_W1; wp.W[7]=out_bi; wp.W[8]=out_W2;
        convw_k<<<dim3(WELEM/256,9),256>>>(wp, Wb);
    }

    auto setg = [&](GM& g, int slot, int m, float* C){
        g.Wh[slot]=WH(m); g.Wm[slot]=WM(m); g.Wl[slot]=WL(m); g.C[slot]=C;
    };

    // ---- leaf level ----
    {
        GM gm; setg(gm,0,0,H);
        gm.Wh[1]=gm.Wh[2]=nullptr; gm.Wm[1]=gm.Wm[2]=nullptr; gm.Wl[1]=gm.Wl[2]=nullptr; gm.C[1]=gm.C[2]=nullptr;
        gemm_k<<<dim3(8,3,1),256>>>(x, gm, nullptr, Bn*Ln, Bn*Ln, 0, 0, 0);
        leaf_k<<<Bn*Ln,128>>>(H, leaf_b, in_ln_g, in_ln_b, ih, isb);
        GM g3; setg(g3,0,1,A); setg(g3,1,2,Bb); setg(g3,2,3,Cm);
        gemm_k<<<dim3(8,3,3),256>>>(ih, g3, nullptr, Bn*Ln, Ln, NCc, 0, 0);
    }

    // ---- inside pass ----
    for (int level=1; level<Ln; level++){
        int Ls = Ln-level, nC = level;
        int rowsBP = Bn*Ls, Pn = rowsBP*nC;
        score_in_k<<<rowsBP,256>>>(ih, isb, Cm, P, level);
        h_k<<<(Pn+3)/4,384>>>(A, Bb, in_B0, H, level, nC, Ls, 0, Pn);
        GM g1; setg(g1,0,4,X);
        g1.Wh[1]=g1.Wh[2]=nullptr; g1.Wm[1]=g1.Wm[2]=nullptr; g1.Wl[1]=g1.Wl[2]=nullptr; g1.C[1]=g1.C[2]=nullptr;
        gemm_k<<<dim3((Pn+127)/128,3,1),256>>>(H, g1, in_B1, Pn, Pn, 0, 0, 1);
        reduceln_k<<<rowsBP,128>>>(X, P, in_ln_g, in_ln_b, ih, nC, Ls, offi(level));
        if (level < Ln-1){
            GM g3; setg(g3,0,1,A); setg(g3,1,2,Bb); setg(g3,2,3,Cm);
            gemm_k<<<dim3((rowsBP+127)/128,3,3),256>>>(ih, g3, nullptr, rowsBP, Ls, NCc, offi(level), 0);
        }
    }

    // ---- outside prep: sib @ out_W1, sib @ out_bi for ALL inside cells ----
    {
        GM g2; setg(g2,0,6,Bb); setg(g2,1,7,Cm);
        g2.Wh[2]=nullptr; g2.Wm[2]=nullptr; g2.Wl[2]=nullptr; g2.C[2]=nullptr;
        gemm_k<<<dim3((Bn*NCc+127)/128,3,2),256>>>(ih, g2, nullptr, Bn*NCc, NCc, NCc, 0, 0);
        root_k<<<Bn,128>>>(root_h, out_ln_g, out_ln_b, oh, osb);
        GM gr; setg(gr,0,5,A);
        gr.Wh[1]=gr.Wh[2]=nullptr; gr.Wm[1]=gr.Wm[2]=nullptr; gr.Wl[1]=gr.Wl[2]=nullptr; gr.C[1]=gr.C[2]=nullptr;
        gemm_k<<<dim3(1,3,1),256>>>(oh, gr, nullptr, Bn, 1, NCc, NCc-1, 0);
    }

    // ---- outside pass ----
    for (int level=Ln-2; level>=0; level--){
        int Ls = Ln-level, nC = Ln-level-1;
        int rowsBP = Bn*Ls, Pn = rowsBP*nC;
        score_out_k<<<rowsBP,256>>>(oh, osb, isb, Cm, P, level);
        h_k<<<(Pn+3)/4,384>>>(A, Bb, out_B0, H, level, nC, Ls, 1, Pn);
        GM g1; setg(g1,0,8,X);
        g1.Wh[1]=g1.Wh[2]=nullptr; g1.Wm[1]=g1.Wm[2]=nullptr; g1.Wl[1]=g1.Wl[2]=nullptr; g1.C[1]=g1.C[2]=nullptr;
        gemm_k<<<dim3((Pn+127)/128,3,1),256>>>(H, g1, out_B1, Pn, Pn, 0, 0, 1);
        reduceln_k<<<rowsBP,128>>>(X, P, out_ln_g, out_ln_b, oh, nC, Ls, offi(level));
        if (level > 0){
            GM g3; setg(g3,0,5,A);
            g3.Wh[1]=g3.Wh[2]=nullptr; g3.Wm[1]=g3.Wm[2]=nullptr; g3.Wl[1]=g3.Wl[2]=nullptr; g3.C[1]=g3.C[2]=nullptr;
            gemm_k<<<dim3((rowsBP+127)/128,3,1),256>>>(oh, g3, nullptr, rowsBP, Ls, NCc, offi(level), 0);
        }
    }
}

// round 13
// speedup vs baseline: 1.1312x; 1.1312x over previous
#include <cuda_runtime.h>
#include <cuda_bf16.h>
#include <math.h>
#include <stdint.h>

#define Bn 32
#define Ln 32
#define NCc 528
#define Dd 384
#define MAXP 32768
#define WELEM (384*384)

// ---------------- device scratch (static, allocation-rule-safe) ----------------
__device__ float g_A [(size_t)Bn*NCc*Dd];
__device__ float g_Bb[(size_t)Bn*NCc*Dd];
__device__ float g_Cm[(size_t)Bn*NCc*Dd];
__device__ float g_H [(size_t)MAXP*Dd];
__device__ float g_X [(size_t)MAXP*Dd];
__device__ float g_P [MAXP];
// 9 weight matrices, each as EXACT 3-way bf16 split (h,m,l) in [n][k] layout
__device__ __nv_bfloat16 g_Wb[(size_t)9*3*WELEM];

__host__ __device__ __forceinline__ int offi(int l){ return l*Ln - (l*(l-1))/2; }

__device__ __forceinline__ float sigma_h_f(float x){
    float s = 1.f/(1.f+expf(-x));
    return x * tanhf(sqrtf(s));
}

__device__ __forceinline__ void in_idx(int level,int pos,int n,int&li,int&ri){
    li = offi(n) + pos;
    ri = offi(level-n-1) + pos + n + 1;
}
__device__ __forceinline__ void out_idx(int level,int pos,int n,int&par,int&sib){
    int T1 = Ln - pos - level - 1;
    if (n < T1){ par = offi(level+n+1)+pos;     sib = offi(n)+pos+level+1; }
    else { int s = n - T1; par = offi(level+s+1)+pos-s-1; sib = offi(s)+pos-s-1; }
}

// EXACT 3-way bf16 split of two fp32 values (packed bf16x2 each):
// x = h + m + l exactly (8+8+8 mantissa bits >= 24; each residual subtraction exact)
__device__ __forceinline__ void cvt3(float x0, float x1, uint32_t& h, uint32_t& m, uint32_t& l){
    asm("cvt.rn.bf16x2.f32 %0, %1, %2;" : "=r"(h) : "f"(x1), "f"(x0));
    float h0 = __uint_as_float(h << 16);
    float h1 = __uint_as_float(h & 0xffff0000u);
    float r0 = x0 - h0, r1 = x1 - h1;
    asm("cvt.rn.bf16x2.f32 %0, %1, %2;" : "=r"(m) : "f"(r1), "f"(r0));
    float m0 = __uint_as_float(m << 16);
    float m1 = __uint_as_float(m & 0xffff0000u);
    float s0 = r0 - m0, s1 = r1 - m1;
    asm("cvt.rn.bf16x2.f32 %0, %1, %2;" : "=r"(l) : "f"(s1), "f"(s0));
}

__device__ __forceinline__ void mma_bf16(float* c, const uint32_t* a, const uint32_t* b){
    asm("mma.sync.aligned.m16n8k16.row.col.f32.bf16.bf16.f32 "
        "{%0,%1,%2,%3}, {%4,%5,%6,%7}, {%8,%9}, {%0,%1,%2,%3};"
        : "+f"(c[0]), "+f"(c[1]), "+f"(c[2]), "+f"(c[3])
        : "r"(a[0]), "r"(a[1]), "r"(a[2]), "r"(a[3]), "r"(b[0]), "r"(b[1]));
}

// 128-thread block reduce of (sum, sumsq)
__device__ __forceinline__ void blockReduce2_128(float& s, float& q){
    __shared__ float shm[8];
    #pragma unroll
    for (int o=16;o>0;o>>=1){
        s += __shfl_xor_sync(0xffffffffu, s, o);
        q += __shfl_xor_sync(0xffffffffu, q, o);
    }
    int w = threadIdx.x>>5;
    if ((threadIdx.x&31)==0){ shm[w]=s; shm[4+w]=q; }
    __syncthreads();
    s = shm[0]+shm[1]+shm[2]+shm[3];
    q = shm[4]+shm[5]+shm[6]+shm[7];
    __syncthreads();
}

// ---------------- weight split: W[k][n] fp32 -> [n][k] bf16 h/m/l (exact) ----------------
struct WP { const float* W[9]; };

__global__ void __launch_bounds__(256) convw_k(WP wp, __nv_bfloat16* out){
    int mtx = blockIdx.y;
    int idx = blockIdx.x*256 + threadIdx.x;   // idx = n*384 + k
    int n = idx / Dd, k = idx - n*Dd;
    float x = wp.W[mtx][(size_t)k*Dd + n];
    __nv_bfloat16 h = __float2bfloat16(x);
    float r = x - __bfloat162float(h);
    __nv_bfloat16 m = __float2bfloat16(r);
    float s = r - __bfloat162float(m);
    __nv_bfloat16 l = __float2bfloat16(s);
    size_t base = (size_t)mtx*3*WELEM;
    out[base + idx]           = h;
    out[base + WELEM + idx]   = m;
    out[base + 2*WELEM + idx] = l;
}

// ---------------- bf16x8 exact-split TC GEMM, 64x128 tile, 2 CTAs/SM ----------------
// row r -> global row g = (r/Ls)*bstride + cellOff + (r%Ls); dense: Ls=rows,bstride=0,cellOff=0
struct GM { const __nv_bfloat16* Wh[3]; const __nv_bfloat16* Wm[3]; const __nv_bfloat16* Wl[3]; float* C[3]; };

__global__ void __launch_bounds__(256,2) gemm_k(
    const float* __restrict__ Abase, GM gm, const float* __restrict__ bias,
    int rows, int Ls, int bstride, int cellOff, int epi)
{
    const __nv_bfloat16* __restrict__ Wh = gm.Wh[blockIdx.z];
    const __nv_bfloat16* __restrict__ Wm = gm.Wm[blockIdx.z];
    const __nv_bfloat16* __restrict__ Wl = gm.Wl[blockIdx.z];
    float* __restrict__ Cb = gm.C[blockIdx.z];

    // k-stride padded to 24 bf16 (48B) -> conflict-free frag LDS and staging STS
    __shared__ __align__(16) __nv_bfloat16 Ash[64*24];
    __shared__ __align__(16) __nv_bfloat16 Asm[64*24];
    __shared__ __align__(16) __nv_bfloat16 Asl[64*24];
    __shared__ __align__(16) __nv_bfloat16 Bsh[128*24];
    __shared__ __align__(16) __nv_bfloat16 Bsm[128*24];
    __shared__ __align__(16) __nv_bfloat16 Bsl[128*24];

    const int tid = threadIdx.x;
    const int bm = blockIdx.x<<6, bn = blockIdx.y<<7;

    // A loader: threads 0..127 -> row tid>>1, k-half (tid&1)*8
    const int arow = tid>>1;
    const int ak = (tid&1)<<3;
    const float* Ap = nullptr;
    if (tid < 128){
        int r = bm + arow;
        if (r < rows){ int b = r/Ls, p = r - b*Ls;
            Ap = Abase + (size_t)(b*bstride + cellOff + p)*Dd + ak; }
    }
    // B loader: all 256 threads -> row tid>>1, k-half (tid&1)*8
    const int brow = tid>>1;
    const int bk = (tid&1)<<3;
    const __nv_bfloat16* Bph = Wh + (size_t)(bn + brow)*Dd + bk;
    const __nv_bfloat16* Bpm = Wm + (size_t)(bn + brow)*Dd + bk;
    const __nv_bfloat16* Bpl = Wl + (size_t)(bn + brow)*Dd + bk;

    // Cr: hh only; Cd: 7 correction products. 64 regs total.
    float Cr[2][4][4], Cd[2][4][4];
    #pragma unroll
    for (int i=0;i<2;i++)
        #pragma unroll
        for (int j=0;j<4;j++)
            #pragma unroll
            for (int q=0;q<4;q++){ Cr[i][j][q]=0.f; Cd[i][j][q]=0.f; }

    const int wid = tid>>5, lane = tid&31;
    const int wm = (wid>>2)<<5;          // 0 or 32
    const int wn = (wid&3)<<5;           // 0,32,64,96
    const int g = lane>>2, tg = lane&3;

    for (int k0=0; k0<Dd; k0+=16){
        // ---- stage A (fp32 -> exact 3-way split) ----
        if (tid < 128){
            float4 a0v = make_float4(0.f,0.f,0.f,0.f), a1v = a0v;
            if (Ap){ a0v = *(const float4*)(Ap + k0); a1v = *(const float4*)(Ap + k0 + 4); }
            uint32_t h0,m0,l0,h1,m1,l1,h2,m2,l2,h3,m3,l3;
            cvt3(a0v.x, a0v.y, h0, m0, l0);
            cvt3(a0v.z, a0v.w, h1, m1, l1);
            cvt3(a1v.x, a1v.y, h2, m2, l2);
            cvt3(a1v.z, a1v.w, h3, m3, l3);
            *(uint4*)&Ash[arow*24+ak] = make_uint4(h0,h1,h2,h3);
            *(uint4*)&Asm[arow*24+ak] = make_uint4(m0,m1,m2,m3);
            *(uint4*)&Asl[arow*24+ak] = make_uint4(l0,l1,l2,l3);
        }
        // ---- stage B (pre-split bf16) ----
        *(uint4*)&Bsh[brow*24+bk] = *(const uint4*)(Bph + k0);
        *(uint4*)&Bsm[brow*24+bk] = *(const uint4*)(Bpm + k0);
        *(uint4*)&Bsl[brow*24+bk] = *(const uint4*)(Bpl + k0);
        __syncthreads();

        // B fragments resident (24 regs)
        uint32_t Bh[4][2], Bm2[4][2], Bl[4][2];
        #pragma unroll
        for (int ni=0;ni<4;ni++){
            int c0 = (wn + ni*8 + g)*24 + tg*2;
            Bh[ni][0]  = *(const uint32_t*)&Bsh[c0];
            Bh[ni][1]  = *(const uint32_t*)&Bsh[c0 + 8];
            Bm2[ni][0] = *(const uint32_t*)&Bsm[c0];
            Bm2[ni][1] = *(const uint32_t*)&Bsm[c0 + 8];
            Bl[ni][0]  = *(const uint32_t*)&Bsl[c0];
            Bl[ni][1]  = *(const uint32_t*)&Bsl[c0 + 8];
        }

        #pragma unroll
        for (int mi=0;mi<2;mi++){
            int r0 = (wm + mi*16 + g)*24 + tg*2;
            uint32_t Ah[4], Am[4], Al[4];
            Ah[0] = *(const uint32_t*)&Ash[r0];
            Ah[1] = *(const uint32_t*)&Ash[r0 + 8*24];
            Ah[2] = *(const uint32_t*)&Ash[r0 + 8];
            Ah[3] = *(const uint32_t*)&Ash[r0 + 8*24 + 8];
            Am[0] = *(const uint32_t*)&Asm[r0];
            Am[1] = *(const uint32_t*)&Asm[r0 + 8*24];
            Am[2] = *(const uint32_t*)&Asm[r0 + 8];
            Am[3] = *(const uint32_t*)&Asm[r0 + 8*24 + 8];
            Al[0] = *(const uint32_t*)&Asl[r0];
            Al[1] = *(const uint32_t*)&Asl[r0 + 8*24];
            Al[2] = *(const uint32_t*)&Asl[r0 + 8];
            Al[3] = *(const uint32_t*)&Asl[r0 + 8*24 + 8];

            // product-type outer, ni inner: same-accumulator MMAs are 4 apart
            // (per-accumulator addition ORDER identical to R10 -> bit-identical result)
            #pragma unroll
            for (int ni=0;ni<4;ni++) mma_bf16(Cr[mi][ni], Ah, Bh[ni]);
            #pragma unroll
            for (int ni=0;ni<4;ni++) mma_bf16(Cd[mi][ni], Ah, Bm2[ni]);
            #pragma unroll
            for (int ni=0;ni<4;ni++) mma_bf16(Cd[mi][ni], Am, Bh[ni]);
            #pragma unroll
            for (int ni=0;ni<4;ni++) mma_bf16(Cd[mi][ni], Am, Bm2[ni]);
            #pragma unroll
            for (int ni=0;ni<4;ni++) mma_bf16(Cd[mi][ni], Ah, Bl[ni]);
            #pragma unroll
            for (int ni=0;ni<4;ni++) mma_bf16(Cd[mi][ni], Al, Bh[ni]);
            #pragma unroll
            for (int ni=0;ni<4;ni++) mma_bf16(Cd[mi][ni], Am, Bl[ni]);
            #pragma unroll
            for (int ni=0;ni<4;ni++) mma_bf16(Cd[mi][ni], Al, Bm2[ni]);
        }
        __syncthreads();
    }

    // ---- epilogue: single merge add per element ----
    #pragma unroll
    for (int mi=0;mi<2;mi++){
        #pragma unroll
        for (int half=0; half<2; half++){
            int r = bm + wm + mi*16 + g + half*8;
            if (r < rows){
                int b = r / Ls; int p = r - b*Ls;
                float* Crow = Cb + (size_t)(b*bstride + cellOff + p)*Dd + bn + wn;
                #pragma unroll
                for (int ni=0;ni<4;ni++){
                    int c0 = ni*8 + tg*2;
                    float v0 = Cr[mi][ni][half*2+0] + Cd[mi][ni][half*2+0];
                    float v1 = Cr[mi][ni][half*2+1] + Cd[mi][ni][half*2+1];
                    if (epi){
                        v0 = sigma_h_f(v0 + bias[bn+wn+c0]);
                        v1 = sigma_h_f(v1 + bias[bn+wn+c0+1]);
                    }
                    *(float2*)(Crow + c0) = make_float2(v0, v1);
                }
            }
        }
    }
}

// ---------------- score + softmax kernels ----------------
__global__ void __launch_bounds__(256) score_in_k(
    const float* __restrict__ ih, float* __restrict__ isb,
    const float* __restrict__ cM, float* __restrict__ P, int level)
{
    int Ls = Ln - level;
    int bp = blockIdx.x;
    int b = bp / Ls, pos = bp - b*Ls;
    int warp = threadIdx.x >> 5, lane = threadIdx.x & 31;
    __shared__ float sc[32];
    for (int n = warp; n < level; n += 8){
        int li, ri; in_idx(level, pos, n, li, ri);
        const float* u = cM + (size_t)(b*NCc + li)*Dd;
        const float* v = ih + (size_t)(b*NCc + ri)*Dd;
        float s = 0.f;
        #pragma unroll 4
        for (int d = lane; d < Dd; d += 32) s += u[d]*v[d];
        #pragma unroll
        for (int o=16;o>0;o>>=1) s += __shfl_xor_sync(0xffffffffu, s, o);
        if (lane==0) sc[n] = s + isb[b*NCc+li] + isb[b*NCc+ri];
    }
    __syncthreads();
    if (warp==0){
        float v = (lane < level) ? sc[lane] : -1e30f;
        float m = v;
        #pragma unroll
        for (int o=16;o>0;o>>=1) m = fmaxf(m, __shfl_xor_sync(0xffffffffu, m, o));
        float e = (lane < level) ? expf(v - m) : 0.f;
        float se = e;
        #pragma unroll
        for (int o=16;o>0;o>>=1) se += __shfl_xor_sync(0xffffffffu, se, o);
        float p = e / se;
        float pb = (lane < level) ? p * v : 0.f;
        #pragma unroll
        for (int o=16;o>0;o>>=1) pb += __shfl_xor_sync(0xffffffffu, pb, o);
        if (lane < level) P[(size_t)bp*level + lane] = p;
        if (lane==0) isb[b*NCc + offi(level) + pos] = pb;
    }
}

__global__ void __launch_bounds__(256) score_out_k(
    const float* __restrict__ oh, float* __restrict__ osb,
    const float* __restrict__ isb, const float* __restrict__ cM,
    float* __restrict__ P, int level)
{
    int Ls = Ln - level, N = Ln - level - 1;
    int bp = blockIdx.x;
    int b = bp / Ls, pos = bp - b*Ls;
    int warp = threadIdx.x >> 5, lane = threadIdx.x & 31;
    __shared__ float sc[32];
    for (int n = warp; n < N; n += 8){
        int par, sib; out_idx(level, pos, n, par, sib);
        const float* u = cM + (size_t)(b*NCc + sib)*Dd;
        const float* v = oh + (size_t)(b*NCc + par)*Dd;
        float s = 0.f;
        #pragma unroll 4
        for (int d = lane; d < Dd; d += 32) s += u[d]*v[d];
        #pragma unroll
        for (int o=16;o>0;o>>=1) s += __shfl_xor_sync(0xffffffffu, s, o);
        if (lane==0) sc[n] = s + isb[b*NCc+sib] + osb[b*NCc+par];
    }
    __syncthreads();
    if (warp==0){
        float v = (lane < N) ? sc[lane] : -1e30f;
        float m = v;
        #pragma unroll
        for (int o=16;o>0;o>>=1) m = fmaxf(m, __shfl_xor_sync(0xffffffffu, m, o));
        float e = (lane < N) ? expf(v - m) : 0.f;
        float se = e;
        #pragma unroll
        for (int o=16;o>0;o>>=1) se += __shfl_xor_sync(0xffffffffu, se, o);
        float p = e / se;
        float pb = (lane < N) ? p * v : 0.f;
        #pragma unroll
        for (int o=16;o>0;o>>=1) pb += __shfl_xor_sync(0xffffffffu, pb, o);
        if (lane < N) P[(size_t)bp*N + lane] = p;
        if (lane==0) osb[b*NCc + offi(level) + pos] = pb;
    }
}

// ---------------- per-pair h = sigma_h(A[a] + B[b] + b0) ----------------
__global__ void __launch_bounds__(384) h_k(
    const float* __restrict__ Abuf, const float* __restrict__ Bbuf,
    const float* __restrict__ b0, float* __restrict__ H,
    int level, int nC, int Ls, int outside, int Pn)
{
    int pl = threadIdx.x / 96;
    int d  = threadIdx.x - pl*96;
    int pair = blockIdx.x*4 + pl;
    if (pair >= Pn) return;
    int bp = pair / nC, n = pair - bp*nC;
    int b = bp / Ls, pos = bp - b*Ls;
    int ia, ib;
    if (!outside) in_idx(level, pos, n, ia, ib);
    else          out_idx(level, pos, n, ia, ib);
    const float4* a  = (const float4*)(Abuf + (size_t)(b*NCc+ia)*Dd);
    const float4* bb = (const float4*)(Bbuf + (size_t)(b*NCc+ib)*Dd);
    const float4* bi = (const float4*)b0;
    float4 av = a[d], bv = bb[d], cv = bi[d];
    float4 h;
    h.x = sigma_h_f(av.x+bv.x+cv.x);
    h.y = sigma_h_f(av.y+bv.y+cv.y);
    h.z = sigma_h_f(av.z+bv.z+cv.z);
    h.w = sigma_h_f(av.w+bv.w+cv.w);
    ((float4*)(H + (size_t)pair*Dd))[d] = h;
}

// ---------------- p-weighted sum over candidates + layer_norm ----------------
__global__ void __launch_bounds__(128) reduceln_k(
    const float* __restrict__ XC, const float* __restrict__ P,
    const float* __restrict__ gamma, const float* __restrict__ beta,
    float* __restrict__ out, int nC, int Ls, int cellOff)
{
    int bp = blockIdx.x;
    int b = bp / Ls, pos = bp - b*Ls;
    int t = threadIdx.x;
    float a0=0.f, a1=0.f, a2=0.f;
    const float* xrow = XC + (size_t)bp*nC*Dd;
    for (int n=0;n<nC;n++){
        float p = P[(size_t)bp*nC + n];
        const float* x = xrow + (size_t)n*Dd;
        a0 += p*x[t]; a1 += p*x[t+128]; a2 += p*x[t+256];
    }
    float s = a0+a1+a2;
    float q = a0*a0+a1*a1+a2*a2;
    blockReduce2_128(s, q);
    float mu = s * (1.f/384.f);
    float var = q * (1.f/384.f) - mu*mu;
    float r = rsqrtf(var + 1e-5f);
    float* o = out + (size_t)(b*NCc + cellOff + pos)*Dd;
    o[t]     = (a0-mu)*r*gamma[t]     + beta[t];
    o[t+128] = (a1-mu)*r*gamma[t+128] + beta[t+128];
    o[t+256] = (a2-mu)*r*gamma[t+256] + beta[t+256];
}

// ---------------- leaf: sigma_h(pre + leaf_b) -> layer_norm -> ih; zero is_ ----------------
__global__ void __launch_bounds__(128) leaf_k(
    const float* __restrict__ pre, const float* __restrict__ lb,
    const float* __restrict__ gamma, const float* __restrict__ beta,
    float* __restrict__ ih, float* __restrict__ isb)
{
    int row = blockIdx.x;         // B*32
    int b = row >> 5, pos = row & 31;
    int t = threadIdx.x;
    const float* pr = pre + (size_t)row*Dd;
    float a0 = sigma_h_f(pr[t]     + lb[t]);
    float a1 = sigma_h_f(pr[t+128] + lb[t+128]);
    float a2 = sigma_h_f(pr[t+256] + lb[t+256]);
    float s = a0+a1+a2, q = a0*a0+a1*a1+a2*a2;
    blockReduce2_128(s, q);
    float mu = s * (1.f/384.f);
    float var = q * (1.f/384.f) - mu*mu;
    float r = rsqrtf(var + 1e-5f);
    float* o = ih + (size_t)(b*NCc + pos)*Dd;
    o[t]     = (a0-mu)*r*gamma[t]     + beta[t];
    o[t+128] = (a1-mu)*r*gamma[t+128] + beta[t+128];
    o[t+256] = (a2-mu)*r*gamma[t+256] + beta[t+256];
    if (t==0) isb[b*NCc + pos] = 0.f;
}

// ---------------- root: oh[:, -1] = layer_norm(root_h); os[:, -1] = 0 ----------------
__global__ void __launch_bounds__(128) root_k(
    const float* __restrict__ rh,
    const float* __restrict__ gamma, const float* __restrict__ beta,
    float* __restrict__ oh, float* __restrict__ osb)
{
    int b = blockIdx.x;
    int t = threadIdx.x;
    float a0 = rh[t], a1 = rh[t+128], a2 = rh[t+256];
    float s = a0+a1+a2, q = a0*a0+a1*a1+a2*a2;
    blockReduce2_128(s, q);
    float mu = s * (1.f/384.f);
    float var = q * (1.f/384.f) - mu*mu;
    float r = rsqrtf(var + 1e-5f);
    float* o = oh + (size_t)(b*NCc + NCc-1)*Dd;
    o[t]     = (a0-mu)*r*gamma[t]     + beta[t];
    o[t+128] = (a1-mu)*r*gamma[t+128] + beta[t+128];
    o[t+256] = (a2-mu)*r*gamma[t+256] + beta[t+256];
    if (t==0) osb[b*NCc + NCc-1] = 0.f;
}

// ---------------- orchestration ----------------
extern "C" void kernel_launch(void* const* d_in, const int* in_sizes, int n_in,
                              void* d_out, int out_size)
{
    (void)in_sizes; (void)n_in; (void)out_size;
    const float* x        = (const float*)d_in[0];
    const float* leaf_W   = (const float*)d_in[1];
    const float* leaf_b   = (const float*)d_in[2];
    const float* in_ln_g  = (const float*)d_in[3];
    const float* in_ln_b  = (const float*)d_in[4];
    const float* out_ln_g = (const float*)d_in[5];
    const float* out_ln_b = (const float*)d_in[6];
    const float* root_h   = (const float*)d_in[7];
    const float* in_bi    = (const float*)d_in[8];
    const float* out_bi   = (const float*)d_in[9];
    const float* in_W0    = (const float*)d_in[10];
    const float* in_W1    = (const float*)d_in[11];
    const float* in_B0    = (const float*)d_in[12];
    const float* in_W2    = (const float*)d_in[13];
    const float* in_B1    = (const float*)d_in[14];
    const float* out_W0   = (const float*)d_in[15];
    const float* out_W1   = (const float*)d_in[16];
    const float* out_B0   = (const float*)d_in[17];
    const float* out_W2   = (const float*)d_in[18];
    const float* out_B1   = (const float*)d_in[19];

    float* ih  = (float*)d_out;
    float* isb = ih  + (size_t)Bn*NCc*Dd;
    float* oh  = isb + (size_t)Bn*NCc;
    float* osb = oh  + (size_t)Bn*NCc*Dd;

    float *A,*Bb,*Cm,*H,*X,*P; __nv_bfloat16* Wb;
    cudaGetSymbolAddress((void**)&A,  g_A);
    cudaGetSymbolAddress((void**)&Bb, g_Bb);
    cudaGetSymbolAddress((void**)&Cm, g_Cm);
    cudaGetSymbolAddress((void**)&H,  g_H);
    cudaGetSymbolAddress((void**)&X,  g_X);
    cudaGetSymbolAddress((void**)&P,  g_P);
    cudaGetSymbolAddress((void**)&Wb, g_Wb);

    auto WH = [&](int m){ return (const __nv_bfloat16*)(Wb + (size_t)m*3*WELEM); };
    auto WM = [&](int m){ return (const __nv_bfloat16*)(Wb + (size_t)m*3*WELEM + WELEM); };
    auto WL = [&](int m){ return (const __nv_bfloat16*)(Wb + (size_t)m*3*WELEM + 2*WELEM); };

    {
        WP wp;
        wp.W[0]=leaf_W; wp.W[1]=in_W0; wp.W[2]=in_W1; wp.W[3]=in_bi; wp.W[4]=in_W2;
        wp.W[5]=out_W0; wp.W[6]=out_W1; wp.W[7]=out_bi; wp.W[8]=out_W2;
        convw_k<<<dim3(WELEM/256,9),256>>>(wp, Wb);
    }

    auto setg = [&](GM& g, int slot, int m, float* C){
        g.Wh[slot]=WH(m); g.Wm[slot]=WM(m); g.Wl[slot]=WL(m); g.C[slot]=C;
    };

    // ---- leaf level ----
    {
        GM gm; setg(gm,0,0,H); setg(gm,1,0,H); setg(gm,2,0,H);
        gemm_k<<<dim3(16,3,1),256>>>(x, gm, nullptr, Bn*Ln, Bn*Ln, 0, 0, 0);
        leaf_k<<<Bn*Ln,128>>>(H, leaf_b, in_ln_g, in_ln_b, ih, isb);
        GM g3; setg(g3,0,1,A); setg(g3,1,2,Bb); setg(g3,2,3,Cm);
        gemm_k<<<dim3(16,3,3),256>>>(ih, g3, nullptr, Bn*Ln, Ln, NCc, 0, 0);
    }

    // ---- inside pass ----
    for (int level=1; level<Ln; level++){
        int Ls = Ln-level, nC = level;
        int rowsBP = Bn*Ls, Pn = rowsBP*nC;
        score_in_k<<<rowsBP,256>>>(ih, isb, Cm, P, level);
        h_k<<<(Pn+3)/4,384>>>(A, Bb, in_B0, H, level, nC, Ls, 0, Pn);
        GM g1; setg(g1,0,4,X); setg(g1,1,4,X); setg(g1,2,4,X);
        gemm_k<<<dim3((Pn+63)/64,3,1),256>>>(H, g1, in_B1, Pn, Pn, 0, 0, 1);
        reduceln_k<<<rowsBP,128>>>(X, P, in_ln_g, in_ln_b, ih, nC, Ls, offi(level));
        if (level < Ln-1){
            GM g3; setg(g3,0,1,A); setg(g3,1,2,Bb); setg(g3,2,3,Cm);
            gemm_k<<<dim3((rowsBP+63)/64,3,3),256>>>(ih, g3, nullptr, rowsBP, Ls, NCc, offi(level), 0);
        }
    }

    // ---- outside prep: sib @ out_W1, sib @ out_bi for ALL inside cells ----
    {
        GM g2; setg(g2,0,6,Bb); setg(g2,1,7,Cm); setg(g2,2,7,Cm);
        gemm_k<<<dim3((Bn*NCc+63)/64,3,2),256>>>(ih, g2, nullptr, Bn*NCc, NCc, NCc, 0, 0);
        root_k<<<Bn,128>>>(root_h, out_ln_g, out_ln_b, oh, osb);
        GM gr; setg(gr,0,5,A); setg(gr,1,5,A); setg(gr,2,5,A);
        gemm_k<<<dim3(1,3,1),256>>>(oh, gr, nullptr, Bn, 1, NCc, NCc-1, 0);
    }

    // ---- outside pass ----
    for (int level=Ln-2; level>=0; level--){
        int Ls = Ln-level, nC = Ln-level-1;
        int rowsBP = Bn*Ls, Pn = rowsBP*nC;
        score_out_k<<<rowsBP,256>>>(oh, osb, isb, Cm, P, level);
        h_k<<<(Pn+3)/4,384>>>(A, Bb, out_B0, H, level, nC, Ls, 1, Pn);
        GM g1; setg(g1,0,8,X); setg(g1,1,8,X); setg(g1,2,8,X);
        gemm_k<<<dim3((Pn+63)/64,3,1),256>>>(H, g1, out_B1, Pn, Pn, 0, 0, 1);
        reduceln_k<<<rowsBP,128>>>(X, P, out_ln_g, out_ln_b, oh, nC, Ls, offi(level));
        if (level > 0){
            GM g3; setg(g3,0,5,A); setg(g3,1,5,A); setg(g3,2,5,A);
            gemm_k<<<dim3((rowsBP+63)/64,3,1),256>>>(oh, g3, nullptr, rowsBP, Ls, NCc, offi(level), 0);
        }
    }
}

// round 14
// speedup vs baseline: 1.1540x; 1.0201x over previous
#include <cuda_runtime.h>
#include <cuda_bf16.h>
#include <math.h>
#include <stdint.h>

#define Bn 32
#define Ln 32
#define NCc 528
#define Dd 384
#define MAXP 32768
#define WELEM (384*384)

// ---------------- device scratch (static, allocation-rule-safe) ----------------
__device__ float g_A [(size_t)Bn*NCc*Dd];
__device__ float g_Bb[(size_t)Bn*NCc*Dd];
__device__ float g_Cm[(size_t)Bn*NCc*Dd];
__device__ float g_H [(size_t)MAXP*Dd];
__device__ float g_X [(size_t)MAXP*Dd];
__device__ float g_P [MAXP];
// 9 weight matrices, each as EXACT 3-way bf16 split (h,m,l) in [n][k] layout
__device__ __nv_bfloat16 g_Wb[(size_t)9*3*WELEM];

__host__ __device__ __forceinline__ int offi(int l){ return l*Ln - (l*(l-1))/2; }

__device__ __forceinline__ float sigma_h_f(float x){
    float s = 1.f/(1.f+expf(-x));
    return x * tanhf(sqrtf(s));
}

__device__ __forceinline__ void in_idx(int level,int pos,int n,int&li,int&ri){
    li = offi(n) + pos;
    ri = offi(level-n-1) + pos + n + 1;
}
__device__ __forceinline__ void out_idx(int level,int pos,int n,int&par,int&sib){
    int T1 = Ln - pos - level - 1;
    if (n < T1){ par = offi(level+n+1)+pos;     sib = offi(n)+pos+level+1; }
    else { int s = n - T1; par = offi(level+s+1)+pos-s-1; sib = offi(s)+pos-s-1; }
}

// EXACT 3-way bf16 split of two fp32 values (packed bf16x2 each):
// x = h + m + l exactly (8+8+8 mantissa bits >= 24; each residual subtraction exact)
__device__ __forceinline__ void cvt3(float x0, float x1, uint32_t& h, uint32_t& m, uint32_t& l){
    asm("cvt.rn.bf16x2.f32 %0, %1, %2;" : "=r"(h) : "f"(x1), "f"(x0));
    float h0 = __uint_as_float(h << 16);
    float h1 = __uint_as_float(h & 0xffff0000u);
    float r0 = x0 - h0, r1 = x1 - h1;
    asm("cvt.rn.bf16x2.f32 %0, %1, %2;" : "=r"(m) : "f"(r1), "f"(r0));
    float m0 = __uint_as_float(m << 16);
    float m1 = __uint_as_float(m & 0xffff0000u);
    float s0 = r0 - m0, s1 = r1 - m1;
    asm("cvt.rn.bf16x2.f32 %0, %1, %2;" : "=r"(l) : "f"(s1), "f"(s0));
}

__device__ __forceinline__ void mma_bf16(float* c, const uint32_t* a, const uint32_t* b){
    asm("mma.sync.aligned.m16n8k16.row.col.f32.bf16.bf16.f32 "
        "{%0,%1,%2,%3}, {%4,%5,%6,%7}, {%8,%9}, {%0,%1,%2,%3};"
        : "+f"(c[0]), "+f"(c[1]), "+f"(c[2]), "+f"(c[3])
        : "r"(a[0]), "r"(a[1]), "r"(a[2]), "r"(a[3]), "r"(b[0]), "r"(b[1]));
}

// 128-thread block reduce of (sum, sumsq)
__device__ __forceinline__ void blockReduce2_128(float& s, float& q){
    __shared__ float shm[8];
    #pragma unroll
    for (int o=16;o>0;o>>=1){
        s += __shfl_xor_sync(0xffffffffu, s, o);
        q += __shfl_xor_sync(0xffffffffu, q, o);
    }
    int w = threadIdx.x>>5;
    if ((threadIdx.x&31)==0){ shm[w]=s; shm[4+w]=q; }
    __syncthreads();
    s = shm[0]+shm[1]+shm[2]+shm[3];
    q = shm[4]+shm[5]+shm[6]+shm[7];
    __syncthreads();
}

// ---------------- weight split: W[k][n] fp32 -> [n][k] bf16 h/m/l (exact) ----------------
struct WP { const float* W[9]; };

__global__ void __launch_bounds__(256) convw_k(WP wp, __nv_bfloat16* out){
    int mtx = blockIdx.y;
    int idx = blockIdx.x*256 + threadIdx.x;   // idx = n*384 + k
    int n = idx / Dd, k = idx - n*Dd;
    float x = wp.W[mtx][(size_t)k*Dd + n];
    __nv_bfloat16 h = __float2bfloat16(x);
    float r = x - __bfloat162float(h);
    __nv_bfloat16 m = __float2bfloat16(r);
    float s = r - __bfloat162float(m);
    __nv_bfloat16 l = __float2bfloat16(s);
    size_t base = (size_t)mtx*3*WELEM;
    out[base + idx]           = h;
    out[base + WELEM + idx]   = m;
    out[base + 2*WELEM + idx] = l;
}

// ---------------- bf16x8 exact-split TC GEMM, 64x128 tile, register prefetch ----------
// row r -> global row g = (r/Ls)*bstride + cellOff + (r%Ls); dense: Ls=rows,bstride=0,cellOff=0
struct GM { const __nv_bfloat16* Wh[3]; const __nv_bfloat16* Wm[3]; const __nv_bfloat16* Wl[3]; float* C[3]; };

__global__ void __launch_bounds__(256) gemm_k(
    const float* __restrict__ Abase, GM gm, const float* __restrict__ bias,
    int rows, int Ls, int bstride, int cellOff, int epi)
{
    const __nv_bfloat16* __restrict__ Wh = gm.Wh[blockIdx.z];
    const __nv_bfloat16* __restrict__ Wm = gm.Wm[blockIdx.z];
    const __nv_bfloat16* __restrict__ Wl = gm.Wl[blockIdx.z];
    float* __restrict__ Cb = gm.C[blockIdx.z];

    // k-stride padded to 24 bf16 (48B) -> conflict-free frag LDS and staging STS
    __shared__ __align__(16) __nv_bfloat16 Ash[64*24];
    __shared__ __align__(16) __nv_bfloat16 Asm[64*24];
    __shared__ __align__(16) __nv_bfloat16 Asl[64*24];
    __shared__ __align__(16) __nv_bfloat16 Bsh[128*24];
    __shared__ __align__(16) __nv_bfloat16 Bsm[128*24];
    __shared__ __align__(16) __nv_bfloat16 Bsl[128*24];

    const int tid = threadIdx.x;
    const int bm = blockIdx.x<<6, bn = blockIdx.y<<7;

    // A loader: threads 0..127 -> row tid>>1, k-half (tid&1)*8
    const int arow = tid>>1;
    const int ak = (tid&1)<<3;
    const float* Ap = nullptr;
    if (tid < 128){
        int r = bm + arow;
        if (r < rows){ int b = r/Ls, p = r - b*Ls;
            Ap = Abase + (size_t)(b*bstride + cellOff + p)*Dd + ak; }
    }
    // B loader: all 256 threads -> row tid>>1, k-half (tid&1)*8
    const int brow = tid>>1;
    const int bk = (tid&1)<<3;
    const __nv_bfloat16* Bph = Wh + (size_t)(bn + brow)*Dd + bk;
    const __nv_bfloat16* Bpm = Wm + (size_t)(bn + brow)*Dd + bk;
    const __nv_bfloat16* Bpl = Wl + (size_t)(bn + brow)*Dd + bk;

    // Cr: hh only; Cd: 7 correction products. 64 regs total.
    float Cr[2][4][4], Cd[2][4][4];
    #pragma unroll
    for (int i=0;i<2;i++)
        #pragma unroll
        for (int j=0;j<4;j++)
            #pragma unroll
            for (int q=0;q<4;q++){ Cr[i][j][q]=0.f; Cd[i][j][q]=0.f; }

    const int wid = tid>>5, lane = tid&31;
    const int wm = (wid>>2)<<5;          // 0 or 32
    const int wn = (wid&3)<<5;           // 0,32,64,96
    const int g = lane>>2, tg = lane&3;

    // ---- prologue: prefetch chunk 0 globals into registers ----
    float4 pa0 = make_float4(0.f,0.f,0.f,0.f), pa1 = pa0;
    uint4 pbh, pbm, pbl;
    if (Ap){ pa0 = *(const float4*)(Ap); pa1 = *(const float4*)(Ap + 4); }
    pbh = *(const uint4*)(Bph);
    pbm = *(const uint4*)(Bpm);
    pbl = *(const uint4*)(Bpl);

    for (int k0=0; k0<Dd; k0+=16){
        // ---- commit staged registers to smem (A: exact 3-way split here) ----
        if (tid < 128){
            uint32_t h0,m0,l0,h1,m1,l1,h2,m2,l2,h3,m3,l3;
            cvt3(pa0.x, pa0.y, h0, m0, l0);
            cvt3(pa0.z, pa0.w, h1, m1, l1);
            cvt3(pa1.x, pa1.y, h2, m2, l2);
            cvt3(pa1.z, pa1.w, h3, m3, l3);
            *(uint4*)&Ash[arow*24+ak] = make_uint4(h0,h1,h2,h3);
            *(uint4*)&Asm[arow*24+ak] = make_uint4(m0,m1,m2,m3);
            *(uint4*)&Asl[arow*24+ak] = make_uint4(l0,l1,l2,l3);
        }
        *(uint4*)&Bsh[brow*24+bk] = pbh;
        *(uint4*)&Bsm[brow*24+bk] = pbm;
        *(uint4*)&Bsl[brow*24+bk] = pbl;
        __syncthreads();

        // ---- prefetch NEXT chunk globals (LDG latency hidden under MMAs) ----
        if (k0 + 16 < Dd){
            if (Ap){ pa0 = *(const float4*)(Ap + k0 + 16); pa1 = *(const float4*)(Ap + k0 + 20); }
            pbh = *(const uint4*)(Bph + k0 + 16);
            pbm = *(const uint4*)(Bpm + k0 + 16);
            pbl = *(const uint4*)(Bpl + k0 + 16);
        }

        // B fragments resident (24 regs)
        uint32_t Bh[4][2], Bm2[4][2], Bl[4][2];
        #pragma unroll
        for (int ni=0;ni<4;ni++){
            int c0 = (wn + ni*8 + g)*24 + tg*2;
            Bh[ni][0]  = *(const uint32_t*)&Bsh[c0];
            Bh[ni][1]  = *(const uint32_t*)&Bsh[c0 + 8];
            Bm2[ni][0] = *(const uint32_t*)&Bsm[c0];
            Bm2[ni][1] = *(const uint32_t*)&Bsm[c0 + 8];
            Bl[ni][0]  = *(const uint32_t*)&Bsl[c0];
            Bl[ni][1]  = *(const uint32_t*)&Bsl[c0 + 8];
        }

        #pragma unroll
        for (int mi=0;mi<2;mi++){
            int r0 = (wm + mi*16 + g)*24 + tg*2;
            uint32_t Ah[4], Am[4], Al[4];
            Ah[0] = *(const uint32_t*)&Ash[r0];
            Ah[1] = *(const uint32_t*)&Ash[r0 + 8*24];
            Ah[2] = *(const uint32_t*)&Ash[r0 + 8];
            Ah[3] = *(const uint32_t*)&Ash[r0 + 8*24 + 8];
            Am[0] = *(const uint32_t*)&Asm[r0];
            Am[1] = *(const uint32_t*)&Asm[r0 + 8*24];
            Am[2] = *(const uint32_t*)&Asm[r0 + 8];
            Am[3] = *(const uint32_t*)&Asm[r0 + 8*24 + 8];
            Al[0] = *(const uint32_t*)&Asl[r0];
            Al[1] = *(const uint32_t*)&Asl[r0 + 8*24];
            Al[2] = *(const uint32_t*)&Asl[r0 + 8];
            Al[3] = *(const uint32_t*)&Asl[r0 + 8*24 + 8];

            // product-type outer, ni inner: same-accumulator MMAs are 4 apart
            // (per-accumulator addition ORDER identical to R10/R12 -> bit-identical result)
            #pragma unroll
            for (int ni=0;ni<4;ni++) mma_bf16(Cr[mi][ni], Ah, Bh[ni]);
            #pragma unroll
            for (int ni=0;ni<4;ni++) mma_bf16(Cd[mi][ni], Ah, Bm2[ni]);
            #pragma unroll
            for (int ni=0;ni<4;ni++) mma_bf16(Cd[mi][ni], Am, Bh[ni]);
            #pragma unroll
            for (int ni=0;ni<4;ni++) mma_bf16(Cd[mi][ni], Am, Bm2[ni]);
            #pragma unroll
            for (int ni=0;ni<4;ni++) mma_bf16(Cd[mi][ni], Ah, Bl[ni]);
            #pragma unroll
            for (int ni=0;ni<4;ni++) mma_bf16(Cd[mi][ni], Al, Bh[ni]);
            #pragma unroll
            for (int ni=0;ni<4;ni++) mma_bf16(Cd[mi][ni], Am, Bl[ni]);
            #pragma unroll
            for (int ni=0;ni<4;ni++) mma_bf16(Cd[mi][ni], Al, Bm2[ni]);
        }
        __syncthreads();
    }

    // ---- epilogue: single merge add per element ----
    #pragma unroll
    for (int mi=0;mi<2;mi++){
        #pragma unroll
        for (int half=0; half<2; half++){
            int r = bm + wm + mi*16 + g + half*8;
            if (r < rows){
                int b = r / Ls; int p = r - b*Ls;
                float* Crow = Cb + (size_t)(b*bstride + cellOff + p)*Dd + bn + wn;
                #pragma unroll
                for (int ni=0;ni<4;ni++){
                    int c0 = ni*8 + tg*2;
                    float v0 = Cr[mi][ni][half*2+0] + Cd[mi][ni][half*2+0];
                    float v1 = Cr[mi][ni][half*2+1] + Cd[mi][ni][half*2+1];
                    if (epi){
                        v0 = sigma_h_f(v0 + bias[bn+wn+c0]);
                        v1 = sigma_h_f(v1 + bias[bn+wn+c0+1]);
                    }
                    *(float2*)(Crow + c0) = make_float2(v0, v1);
                }
            }
        }
    }
}

// ---------------- score + softmax kernels ----------------
__global__ void __launch_bounds__(256) score_in_k(
    const float* __restrict__ ih, float* __restrict__ isb,
    const float* __restrict__ cM, float* __restrict__ P, int level)
{
    int Ls = Ln - level;
    int bp = blockIdx.x;
    int b = bp / Ls, pos = bp - b*Ls;
    int warp = threadIdx.x >> 5, lane = threadIdx.x & 31;
    __shared__ float sc[32];
    for (int n = warp; n < level; n += 8){
        int li, ri; in_idx(level, pos, n, li, ri);
        const float* u = cM + (size_t)(b*NCc + li)*Dd;
        const float* v = ih + (size_t)(b*NCc + ri)*Dd;
        float s = 0.f;
        #pragma unroll 4
        for (int d = lane; d < Dd; d += 32) s += u[d]*v[d];
        #pragma unroll
        for (int o=16;o>0;o>>=1) s += __shfl_xor_sync(0xffffffffu, s, o);
        if (lane==0) sc[n] = s + isb[b*NCc+li] + isb[b*NCc+ri];
    }
    __syncthreads();
    if (warp==0){
        float v = (lane < level) ? sc[lane] : -1e30f;
        float m = v;
        #pragma unroll
        for (int o=16;o>0;o>>=1) m = fmaxf(m, __shfl_xor_sync(0xffffffffu, m, o));
        float e = (lane < level) ? expf(v - m) : 0.f;
        float se = e;
        #pragma unroll
        for (int o=16;o>0;o>>=1) se += __shfl_xor_sync(0xffffffffu, se, o);
        float p = e / se;
        float pb = (lane < level) ? p * v : 0.f;
        #pragma unroll
        for (int o=16;o>0;o>>=1) pb += __shfl_xor_sync(0xffffffffu, pb, o);
        if (lane < level) P[(size_t)bp*level + lane] = p;
        if (lane==0) isb[b*NCc + offi(level) + pos] = pb;
    }
}

__global__ void __launch_bounds__(256) score_out_k(
    const float* __restrict__ oh, float* __restrict__ osb,
    const float* __restrict__ isb, const float* __restrict__ cM,
    float* __restrict__ P, int level)
{
    int Ls = Ln - level, N = Ln - level - 1;
    int bp = blockIdx.x;
    int b = bp / Ls, pos = bp - b*Ls;
    int warp = threadIdx.x >> 5, lane = threadIdx.x & 31;
    __shared__ float sc[32];
    for (int n = warp; n < N; n += 8){
        int par, sib; out_idx(level, pos, n, par, sib);
        const float* u = cM + (size_t)(b*NCc + sib)*Dd;
        const float* v = oh + (size_t)(b*NCc + par)*Dd;
        float s = 0.f;
        #pragma unroll 4
        for (int d = lane; d < Dd; d += 32) s += u[d]*v[d];
        #pragma unroll
        for (int o=16;o>0;o>>=1) s += __shfl_xor_sync(0xffffffffu, s, o);
        if (lane==0) sc[n] = s + isb[b*NCc+sib] + osb[b*NCc+par];
    }
    __syncthreads();
    if (warp==0){
        float v = (lane < N) ? sc[lane] : -1e30f;
        float m = v;
        #pragma unroll
        for (int o=16;o>0;o>>=1) m = fmaxf(m, __shfl_xor_sync(0xffffffffu, m, o));
        float e = (lane < N) ? expf(v - m) : 0.f;
        float se = e;
        #pragma unroll
        for (int o=16;o>0;o>>=1) se += __shfl_xor_sync(0xffffffffu, se, o);
        float p = e / se;
        float pb = (lane < N) ? p * v : 0.f;
        #pragma unroll
        for (int o=16;o>0;o>>=1) pb += __shfl_xor_sync(0xffffffffu, pb, o);
        if (lane < N) P[(size_t)bp*N + lane] = p;
        if (lane==0) osb[b*NCc + offi(level) + pos] = pb;
    }
}

// ---------------- per-pair h = sigma_h(A[a] + B[b] + b0) ----------------
__global__ void __launch_bounds__(384) h_k(
    const float* __restrict__ Abuf, const float* __restrict__ Bbuf,
    const float* __restrict__ b0, float* __restrict__ H,
    int level, int nC, int Ls, int outside, int Pn)
{
    int pl = threadIdx.x / 96;
    int d  = threadIdx.x - pl*96;
    int pair = blockIdx.x*4 + pl;
    if (pair >= Pn) return;
    int bp = pair / nC, n = pair - bp*nC;
    int b = bp / Ls, pos = bp - b*Ls;
    int ia, ib;
    if (!outside) in_idx(level, pos, n, ia, ib);
    else          out_idx(level, pos, n, ia, ib);
    const float4* a  = (const float4*)(Abuf + (size_t)(b*NCc+ia)*Dd);
    const float4* bb = (const float4*)(Bbuf + (size_t)(b*NCc+ib)*Dd);
    const float4* bi = (const float4*)b0;
    float4 av = a[d], bv = bb[d], cv = bi[d];
    float4 h;
    h.x = sigma_h_f(av.x+bv.x+cv.x);
    h.y = sigma_h_f(av.y+bv.y+cv.y);
    h.z = sigma_h_f(av.z+bv.z+cv.z);
    h.w = sigma_h_f(av.w+bv.w+cv.w);
    ((float4*)(H + (size_t)pair*Dd))[d] = h;
}

// ---------------- p-weighted sum over candidates + layer_norm ----------------
__global__ void __launch_bounds__(128) reduceln_k(
    const float* __restrict__ XC, const float* __restrict__ P,
    const float* __restrict__ gamma, const float* __restrict__ beta,
    float* __restrict__ out, int nC, int Ls, int cellOff)
{
    int bp = blockIdx.x;
    int b = bp / Ls, pos = bp - b*Ls;
    int t = threadIdx.x;
    float a0=0.f, a1=0.f, a2=0.f;
    const float* xrow = XC + (size_t)bp*nC*Dd;
    for (int n=0;n<nC;n++){
        float p = P[(size_t)bp*nC + n];
        const float* x = xrow + (size_t)n*Dd;
        a0 += p*x[t]; a1 += p*x[t+128]; a2 += p*x[t+256];
    }
    float s = a0+a1+a2;
    float q = a0*a0+a1*a1+a2*a2;
    blockReduce2_128(s, q);
    float mu = s * (1.f/384.f);
    float var = q * (1.f/384.f) - mu*mu;
    float r = rsqrtf(var + 1e-5f);
    float* o = out + (size_t)(b*NCc + cellOff + pos)*Dd;
    o[t]     = (a0-mu)*r*gamma[t]     + beta[t];
    o[t+128] = (a1-mu)*r*gamma[t+128] + beta[t+128];
    o[t+256] = (a2-mu)*r*gamma[t+256] + beta[t+256];
}

// ---------------- leaf: sigma_h(pre + leaf_b) -> layer_norm -> ih; zero is_ ----------------
__global__ void __launch_bounds__(128) leaf_k(
    const float* __restrict__ pre, const float* __restrict__ lb,
    const float* __restrict__ gamma, const float* __restrict__ beta,
    float* __restrict__ ih, float* __restrict__ isb)
{
    int row = blockIdx.x;         // B*32
    int b = row >> 5, pos = row & 31;
    int t = threadIdx.x;
    const float* pr = pre + (size_t)row*Dd;
    float a0 = sigma_h_f(pr[t]     + lb[t]);
    float a1 = sigma_h_f(pr[t+128] + lb[t+128]);
    float a2 = sigma_h_f(pr[t+256] + lb[t+256]);
    float s = a0+a1+a2, q = a0*a0+a1*a1+a2*a2;
    blockReduce2_128(s, q);
    float mu = s * (1.f/384.f);
    float var = q * (1.f/384.f) - mu*mu;
    float r = rsqrtf(var + 1e-5f);
    float* o = ih + (size_t)(b*NCc + pos)*Dd;
    o[t]     = (a0-mu)*r*gamma[t]     + beta[t];
    o[t+128] = (a1-mu)*r*gamma[t+128] + beta[t+128];
    o[t+256] = (a2-mu)*r*gamma[t+256] + beta[t+256];
    if (t==0) isb[b*NCc + pos] = 0.f;
}

// ---------------- root: oh[:, -1] = layer_norm(root_h); os[:, -1] = 0 ----------------
__global__ void __launch_bounds__(128) root_k(
    const float* __restrict__ rh,
    const float* __restrict__ gamma, const float* __restrict__ beta,
    float* __restrict__ oh, float* __restrict__ osb)
{
    int b = blockIdx.x;
    int t = threadIdx.x;
    float a0 = rh[t], a1 = rh[t+128], a2 = rh[t+256];
    float s = a0+a1+a2, q = a0*a0+a1*a1+a2*a2;
    blockReduce2_128(s, q);
    float mu = s * (1.f/384.f);
    float var = q * (1.f/384.f) - mu*mu;
    float r = rsqrtf(var + 1e-5f);
    float* o = oh + (size_t)(b*NCc + NCc-1)*Dd;
    o[t]     = (a0-mu)*r*gamma[t]     + beta[t];
    o[t+128] = (a1-mu)*r*gamma[t+128] + beta[t+128];
    o[t+256] = (a2-mu)*r*gamma[t+256] + beta[t+256];
    if (t==0) osb[b*NCc + NCc-1] = 0.f;
}

// ---------------- orchestration ----------------
extern "C" void kernel_launch(void* const* d_in, const int* in_sizes, int n_in,
                              void* d_out, int out_size)
{
    (void)in_sizes; (void)n_in; (void)out_size;
    const float* x        = (const float*)d_in[0];
    const float* leaf_W   = (const float*)d_in[1];
    const float* leaf_b   = (const float*)d_in[2];
    const float* in_ln_g  = (const float*)d_in[3];
    const float* in_ln_b  = (const float*)d_in[4];
    const float* out_ln_g = (const float*)d_in[5];
    const float* out_ln_b = (const float*)d_in[6];
    const float* root_h   = (const float*)d_in[7];
    const float* in_bi    = (const float*)d_in[8];
    const float* out_bi   = (const float*)d_in[9];
    const float* in_W0    = (const float*)d_in[10];
    const float* in_W1    = (const float*)d_in[11];
    const float* in_B0    = (const float*)d_in[12];
    const float* in_W2    = (const float*)d_in[13];
    const float* in_B1    = (const float*)d_in[14];
    const float* out_W0   = (const float*)d_in[15];
    const float* out_W1   = (const float*)d_in[16];
    const float* out_B0   = (const float*)d_in[17];
    const float* out_W2   = (const float*)d_in[18];
    const float* out_B1   = (const float*)d_in[19];

    float* ih  = (float*)d_out;
    float* isb = ih  + (size_t)Bn*NCc*Dd;
    float* oh  = isb + (size_t)Bn*NCc;
    float* osb = oh  + (size_t)Bn*NCc*Dd;

    float *A,*Bb,*Cm,*H,*X,*P; __nv_bfloat16* Wb;
    cudaGetSymbolAddress((void**)&A,  g_A);
    cudaGetSymbolAddress((void**)&Bb, g_Bb);
    cudaGetSymbolAddress((void**)&Cm, g_Cm);
    cudaGetSymbolAddress((void**)&H,  g_H);
    cudaGetSymbolAddress((void**)&X,  g_X);
    cudaGetSymbolAddress((void**)&P,  g_P);
    cudaGetSymbolAddress((void**)&Wb, g_Wb);

    auto WH = [&](int m){ return (const __nv_bfloat16*)(Wb + (size_t)m*3*WELEM); };
    auto WM = [&](int m){ return (const __nv_bfloat16*)(Wb + (size_t)m*3*WELEM + WELEM); };
    auto WL = [&](int m){ return (const __nv_bfloat16*)(Wb + (size_t)m*3*WELEM + 2*WELEM); };

    {
        WP wp;
        wp.W[0]=leaf_W; wp.W[1]=in_W0; wp.W[2]=in_W1; wp.W[3]=in_bi; wp.W[4]=in_W2;
        wp.W[5]=out_W0; wp.W[6]=out_W1; wp.W[7]=out_bi; wp.W[8]=out_W2;
        convw_k<<<dim3(WELEM/256,9),256>>>(wp, Wb);
    }

    auto setg = [&](GM& g, int slot, int m, float* C){
        g.Wh[slot]=WH(m); g.Wm[slot]=WM(m); g.Wl[slot]=WL(m); g.C[slot]=C;
    };

    // ---- leaf level ----
    {
        GM gm; setg(gm,0,0,H); setg(gm,1,0,H); setg(gm,2,0,H);
        gemm_k<<<dim3(16,3,1),256>>>(x, gm, nullptr, Bn*Ln, Bn*Ln, 0, 0, 0);
        leaf_k<<<Bn*Ln,128>>>(H, leaf_b, in_ln_g, in_ln_b, ih, isb);
        GM g3; setg(g3,0,1,A); setg(g3,1,2,Bb); setg(g3,2,3,Cm);
        gemm_k<<<dim3(16,3,3),256>>>(ih, g3, nullptr, Bn*Ln, Ln, NCc, 0, 0);
    }

    // ---- inside pass ----
    for (int level=1; level<Ln; level++){
        int Ls = Ln-level, nC = level;
        int rowsBP = Bn*Ls, Pn = rowsBP*nC;
        score_in_k<<<rowsBP,256>>>(ih, isb, Cm, P, level);
        h_k<<<(Pn+3)/4,384>>>(A, Bb, in_B0, H, level, nC, Ls, 0, Pn);
        GM g1; setg(g1,0,4,X); setg(g1,1,4,X); setg(g1,2,4,X);
        gemm_k<<<dim3((Pn+63)/64,3,1),256>>>(H, g1, in_B1, Pn, Pn, 0, 0, 1);
        reduceln_k<<<rowsBP,128>>>(X, P, in_ln_g, in_ln_b, ih, nC, Ls, offi(level));
        if (level < Ln-1){
            GM g3; setg(g3,0,1,A); setg(g3,1,2,Bb); setg(g3,2,3,Cm);
            gemm_k<<<dim3((rowsBP+63)/64,3,3),256>>>(ih, g3, nullptr, rowsBP, Ls, NCc, offi(level), 0);
        }
    }

    // ---- outside prep: sib @ out_W1, sib @ out_bi for ALL inside cells ----
    {
        GM g2; setg(g2,0,6,Bb); setg(g2,1,7,Cm); setg(g2,2,7,Cm);
        gemm_k<<<dim3((Bn*NCc+63)/64,3,2),256>>>(ih, g2, nullptr, Bn*NCc, NCc, NCc, 0, 0);
        root_k<<<Bn,128>>>(root_h, out_ln_g, out_ln_b, oh, osb);
        GM gr; setg(gr,0,5,A); setg(gr,1,5,A); setg(gr,2,5,A);
        gemm_k<<<dim3(1,3,1),256>>>(oh, gr, nullptr, Bn, 1, NCc, NCc-1, 0);
    }

    // ---- outside pass ----
    for (int level=Ln-2; level>=0; level--){
        int Ls = Ln-level, nC = Ln-level-1;
        int rowsBP = Bn*Ls, Pn = rowsBP*nC;
        score_out_k<<<rowsBP,256>>>(oh, osb, isb, Cm, P, level);
        h_k<<<(Pn+3)/4,384>>>(A, Bb, out_B0, H, level, nC, Ls, 1, Pn);
        GM g1; setg(g1,0,8,X); setg(g1,1,8,X); setg(g1,2,8,X);
        gemm_k<<<dim3((Pn+63)/64,3,1),256>>>(H, g1, out_B1, Pn, Pn, 0, 0, 1);
        reduceln_k<<<rowsBP,128>>>(X, P, out_ln_g, out_ln_b, oh, nC, Ls, offi(level));
        if (level > 0){
            GM g3; setg(g3,0,5,A); setg(g3,1,5,A); setg(g3,2,5,A);
            gemm_k<<<dim3((rowsBP+63)/64,3,1),256>>>(oh, g3, nullptr, rowsBP, Ls, NCc, offi(level), 0);
        }
    }
}